// round 17
// baseline (speedup 1.0000x reference)
#include <cuda_runtime.h>
#include <cuda_bf16.h>
#include <math.h>
#include <stdint.h>

// Problem dims
#define QL 2048
#define CTX 2048
#define HDIM 4096
#define NH 32
#define NKV 8
#define HD 128
#define KVLEN (CTX + QL)          // 4096
#define KVSTRIDE (KVLEN * HD)     // elements per kv head

#define QSCALE (0.08838834764831845f * 1.4426950408889634f)   // (1/sqrt(128))*log2(e)

// ---------------------------------------------------------------------------
// Scratch (__device__ globals; allocation-free rule)
// ---------------------------------------------------------------------------
__device__ float g_Q[(size_t)QL * HDIM];

__device__ __nv_bfloat16 g_hidHi[(size_t)QL * HDIM],  g_hidLo[(size_t)QL * HDIM];
__device__ __nv_bfloat16 g_tgtHi[(size_t)CTX * HDIM], g_tgtLo[(size_t)CTX * HDIM];
__device__ __nv_bfloat16 g_WqHi[(size_t)HDIM * HDIM], g_WqLo[(size_t)HDIM * HDIM];
__device__ __nv_bfloat16 g_WkHi[(size_t)NKV * HD * HDIM], g_WkLo[(size_t)NKV * HD * HDIM];
__device__ __nv_bfloat16 g_WvHi[(size_t)NKV * HD * HDIM], g_WvLo[(size_t)NKV * HD * HDIM];
__device__ __nv_bfloat16 g_WoHi[(size_t)HDIM * HDIM], g_WoLo[(size_t)HDIM * HDIM];
__device__ __nv_bfloat16 g_AHi[(size_t)QL * HDIM],  g_ALo[(size_t)QL * HDIM];

__device__ __nv_bfloat16 g_Kh[(size_t)NKV * KVLEN * HD], g_Kl[(size_t)NKV * KVLEN * HD];
__device__ __nv_bfloat16 g_Vh[(size_t)NKV * KVLEN * HD], g_Vl[(size_t)NKV * KVLEN * HD];

// ---------------------------------------------------------------------------
// PTX helpers (base sm_103-legal only: cp.async, ldmatrix, mma.sync)
// ---------------------------------------------------------------------------
__device__ __forceinline__ uint32_t smem_u32(const void* p) {
    uint32_t a;
    asm("{ .reg .u64 t; cvta.to.shared.u64 t, %1; cvt.u32.u64 %0, t; }" : "=r"(a) : "l"(p));
    return a;
}
#define CP_ASYNC16(dst, src) \
    asm volatile("cp.async.cg.shared.global [%0], [%1], 16;" :: "r"(dst), "l"(src))
#define CP_COMMIT() asm volatile("cp.async.commit_group;" ::: "memory")
#define CP_WAIT1()  asm volatile("cp.async.wait_group 1;" ::: "memory")

#define LDSM_X4(r0, r1, r2, r3, addr) \
    asm volatile("ldmatrix.sync.aligned.m8n8.x4.shared.b16 {%0,%1,%2,%3}, [%4];" \
                 : "=r"(r0), "=r"(r1), "=r"(r2), "=r"(r3) : "r"(addr))
#define LDSM_X4_T(r0, r1, r2, r3, addr) \
    asm volatile("ldmatrix.sync.aligned.m8n8.x4.trans.shared.b16 {%0,%1,%2,%3}, [%4];" \
                 : "=r"(r0), "=r"(r1), "=r"(r2), "=r"(r3) : "r"(addr))

#define MMA16816(d, a, b) \
    asm volatile("mma.sync.aligned.m16n8k16.row.col.f32.bf16.bf16.f32 " \
                 "{%0,%1,%2,%3}, {%4,%5,%6,%7}, {%8,%9}, {%0,%1,%2,%3};" \
                 : "+f"((d)[0]), "+f"((d)[1]), "+f"((d)[2]), "+f"((d)[3]) \
                 : "r"((a)[0]), "r"((a)[1]), "r"((a)[2]), "r"((a)[3]), \
                   "r"((b)[0]), "r"((b)[1]))

#define PACK_BF16X2(r, flo, fhi) \
    asm("cvt.rn.bf16x2.f32 %0, %1, %2;" : "=r"(r) : "f"(fhi), "f"(flo))

// split two floats -> (hi bf16x2, lo bf16x2)
__device__ __forceinline__ void bsplit2(float f0, float f1,
                                        uint32_t& hi, uint32_t& lo) {
    PACK_BF16X2(hi, f0, f1);
    float r0 = f0 - __uint_as_float(hi << 16);
    float r1 = f1 - __uint_as_float(hi & 0xFFFF0000u);
    PACK_BF16X2(lo, r0, r1);
}

// ---------------------------------------------------------------------------
// bf16-split HMMA GEMM core, MODE as template parameter (per-kernel regalloc).
// MODE 0: C row-major [., ldn]
// MODE 1: K projection with fused RoPE -> g_Kh/g_Kl
// MODE 2: V bf16 hi/lo split -> g_Vh/g_Vl
// ---------------------------------------------------------------------------
#define TM 128
#define TN 256
#define TK 32
#define A_TILE_B (128 * 80)
#define B_TILE_B (256 * 80)
#define OFF_ALO A_TILE_B
#define OFF_BHI (2 * A_TILE_B)
#define OFF_BLO (2 * A_TILE_B + B_TILE_B)
#define STG_B (2 * A_TILE_B + 2 * B_TILE_B)   // 61440
#define SMEM_G (3 * STG_B)                // 184320
#define KSTR 264                          // fp32 staging row stride (floats)

__device__ __forceinline__ void g_load_stage(
    uint32_t sb, int stage, int tid,
    const __nv_bfloat16* aHi, const __nv_bfloat16* aLo,
    const __nv_bfloat16* bHi, const __nv_bfloat16* bLo,
    int bm, int bn, int K, int k0)
{
    const uint32_t st = sb + stage * STG_B;
#pragma unroll
    for (int t = 0; t < 12; t++) {
        int idx = tid + 256 * t;
        const __nv_bfloat16* base;
        int grow, r;
        uint32_t toff;
        if (idx < 512)       { base = aHi; r = idx >> 2;           grow = bm + r; toff = 0; }
        else if (idx < 1024) { base = aLo; r = (idx - 512) >> 2;   grow = bm + r; toff = OFF_ALO; }
        else if (idx < 2048) { base = bHi; r = (idx - 1024) >> 2;  grow = bn + r; toff = OFF_BHI; }
        else                 { base = bLo; r = (idx - 2048) >> 2;  grow = bn + r; toff = OFF_BLO; }
        int c = idx & 3;
        const char* src = (const char*)(base + (size_t)grow * K + k0 + c * 8);
        uint32_t dst = st + toff + r * 80 + c * 16;
        CP_ASYNC16(dst, src);
    }
}

template <int MODE>
__device__ __forceinline__ void gemm_core(
    const __nv_bfloat16* __restrict__ aHi, const __nv_bfloat16* __restrict__ aLo,
    const __nv_bfloat16* __restrict__ bHi, const __nv_bfloat16* __restrict__ bLo,
    int bm, int bn, int K,
    float* __restrict__ C, int ldn, int pos0,
    const float* __restrict__ cosb, const float* __restrict__ sinb)
{
    extern __shared__ char smem[];
    const uint32_t sb = smem_u32(smem);
    const int tid = threadIdx.x;
    const int wid = tid >> 5;
    const int lane = tid & 31;
    const int wm = (wid >> 2) * 64;
    const int wn = (wid & 3) * 64;
    const int nch = K / TK;

    float acc[4][8][4];
#pragma unroll
    for (int mt = 0; mt < 4; mt++)
#pragma unroll
        for (int nt = 0; nt < 8; nt++)
#pragma unroll
            for (int i = 0; i < 4; i++) acc[mt][nt][i] = 0.0f;

    g_load_stage(sb, 0, tid, aHi, aLo, bHi, bLo, bm, bn, K, 0);
    CP_COMMIT();
    g_load_stage(sb, 1, tid, aHi, aLo, bHi, bLo, bm, bn, K, TK);
    CP_COMMIT();

    int stage = 0;
    for (int c = 0; c < nch; c++) {
        CP_WAIT1();
        __syncthreads();
        if (c + 2 < nch) {
            int s2 = stage + 2; if (s2 >= 3) s2 -= 3;
            g_load_stage(sb, s2, tid, aHi, aLo, bHi, bLo, bm, bn, K, (c + 2) * TK);
        }
        CP_COMMIT();

        const uint32_t st = sb + stage * STG_B;
#pragma unroll
        for (int kg = 0; kg < 2; kg++) {
            uint32_t ah[4][4], al[4][4];
            const int acol = kg * 16 + (lane >> 4) * 8;
#pragma unroll
            for (int mt = 0; mt < 4; mt++) {
                int row = wm + mt * 16 + (lane & 15);
                uint32_t ad = st + row * 80 + acol * 2;
                LDSM_X4(ah[mt][0], ah[mt][1], ah[mt][2], ah[mt][3], ad);
                LDSM_X4(al[mt][0], al[mt][1], al[mt][2], al[mt][3], ad + OFF_ALO);
            }
            const int bcol = kg * 16 + ((lane >> 3) & 1) * 8;
#pragma unroll
            for (int p = 0; p < 4; p++) {
                uint32_t bh[4], bl[4];
                const int brow = wn + p * 16 + (lane & 7) + (lane >> 4) * 8;
                uint32_t bd = st + OFF_BHI + brow * 80 + bcol * 2;
                LDSM_X4(bh[0], bh[1], bh[2], bh[3], bd);
                LDSM_X4(bl[0], bl[1], bl[2], bl[3], bd + (OFF_BLO - OFF_BHI));
#pragma unroll
                for (int mt = 0; mt < 4; mt++) {
                    MMA16816(acc[mt][2 * p],     ah[mt], &bh[0]);
                    MMA16816(acc[mt][2 * p + 1], ah[mt], &bh[2]);
                    MMA16816(acc[mt][2 * p],     ah[mt], &bl[0]);
                    MMA16816(acc[mt][2 * p + 1], ah[mt], &bl[2]);
                    MMA16816(acc[mt][2 * p],     al[mt], &bh[0]);
                    MMA16816(acc[mt][2 * p + 1], al[mt], &bh[2]);
                }
            }
        }
        stage++; if (stage >= 3) stage = 0;
        __syncthreads();
    }

    if (MODE == 0) {
#pragma unroll
        for (int mt = 0; mt < 4; mt++)
#pragma unroll
            for (int nt = 0; nt < 8; nt++) {
                int row = bm + wm + mt * 16 + (lane >> 2);
                int col = bn + wn + nt * 8 + (lane & 3) * 2;
                *(float2*)(C + (size_t)row * ldn + col) =
                    make_float2(acc[mt][nt][0], acc[mt][nt][1]);
                *(float2*)(C + (size_t)(row + 8) * ldn + col) =
                    make_float2(acc[mt][nt][2], acc[mt][nt][3]);
            }
    } else if (MODE == 2) {
#pragma unroll
        for (int mt = 0; mt < 4; mt++)
#pragma unroll
            for (int nt = 0; nt < 8; nt++) {
                int row = bm + wm + mt * 16 + (lane >> 2);
                int col = bn + wn + nt * 8 + (lane & 3) * 2;
                const int head = col >> 7;
                const int hd = col & 127;
                const size_t e0 = (size_t)head * KVSTRIDE + (size_t)(pos0 + row) * HD + hd;
                const size_t e1 = (size_t)head * KVSTRIDE + (size_t)(pos0 + row + 8) * HD + hd;
                uint32_t h0, h1, l0, l1;
                bsplit2(acc[mt][nt][0], acc[mt][nt][1], h0, l0);
                bsplit2(acc[mt][nt][2], acc[mt][nt][3], h1, l1);
                ((uint32_t*)g_Vh)[e0 >> 1] = h0;
                ((uint32_t*)g_Vl)[e0 >> 1] = l0;
                ((uint32_t*)g_Vh)[e1 >> 1] = h1;
                ((uint32_t*)g_Vl)[e1 >> 1] = l1;
            }
    } else {
        // MODE 1: K projection — stage fp32 tile, fused RoPE, bf16 hi/lo out.
        float* stg = (float*)smem;
#pragma unroll
        for (int mt = 0; mt < 4; mt++)
#pragma unroll
            for (int nt = 0; nt < 8; nt++) {
                int r0 = wm + mt * 16 + (lane >> 2);
                int lc = wn + nt * 8 + (lane & 3) * 2;
                stg[r0 * KSTR + lc]     = acc[mt][nt][0];
                stg[r0 * KSTR + lc + 1] = acc[mt][nt][1];
                stg[(r0 + 8) * KSTR + lc]     = acc[mt][nt][2];
                stg[(r0 + 8) * KSTR + lc + 1] = acc[mt][nt][3];
            }
        __syncthreads();
#pragma unroll
        for (int t = 0; t < 32; t++) {
            int idx = tid + 256 * t;
            int hd = (idx & 31) * 2;
            int hl = (idx >> 5) & 1;
            int r  = idx >> 6;
            int lc = hl * 128 + hd;
            float x1a = stg[r * KSTR + lc];
            float x1b = stg[r * KSTR + lc + 1];
            float x2a = stg[r * KSTR + lc + 64];
            float x2b = stg[r * KSTR + lc + 65];
            const int pos = pos0 + bm + r;
            float2 c1 = *(const float2*)(cosb + (size_t)pos * HD + hd);
            float2 s1 = *(const float2*)(sinb + (size_t)pos * HD + hd);
            float2 c2 = *(const float2*)(cosb + (size_t)pos * HD + hd + 64);
            float2 s2 = *(const float2*)(sinb + (size_t)pos * HD + hd + 64);
            float y1a = x1a * c1.x - x2a * s1.x;
            float y1b = x1b * c1.y - x2b * s1.y;
            float y2a = x2a * c2.x + x1a * s2.x;
            float y2b = x2b * c2.y + x1b * s2.y;
            uint32_t h1, l1, h2, l2;
            bsplit2(y1a, y1b, h1, l1);
            bsplit2(y2a, y2b, h2, l2);
            const int head = (bn >> 7) + hl;
            const size_t e1 = (size_t)head * KVSTRIDE + (size_t)pos * HD + hd;
            ((uint32_t*)g_Kh)[e1 >> 1] = h1;
            ((uint32_t*)g_Kl)[e1 >> 1] = l1;
            ((uint32_t*)g_Kh)[(e1 + 64) >> 1] = h2;
            ((uint32_t*)g_Kl)[(e1 + 64) >> 1] = l2;
        }
    }
}

// Q projection: 256 CTAs
__global__ __launch_bounds__(256, 1)
void gemm_q(float* __restrict__ Qo)
{
    const int bm = blockIdx.y * TM;
    const int bn = blockIdx.x * TN;
    gemm_core<0>(g_hidHi, g_hidLo, g_WqHi, g_WqLo, bm, bn, HDIM, Qo, HDIM, 0,
                 nullptr, nullptr);
}

// K projections (ctx + noise) with fused RoPE: 128 CTAs (z = source)
__global__ __launch_bounds__(256, 1)
void gemm_k(const float* __restrict__ cosb, const float* __restrict__ sinb)
{
    const __nv_bfloat16 *aHi, *aLo;
    int pos0;
    if (blockIdx.z) { aHi = g_hidHi; aLo = g_hidLo; pos0 = CTX; }
    else            { aHi = g_tgtHi; aLo = g_tgtLo; pos0 = 0; }
    gemm_core<1>(aHi, aLo, g_WkHi, g_WkLo, blockIdx.y * TM, blockIdx.x * TN,
                 HDIM, nullptr, 0, pos0, cosb, sinb);
}

// V projections (ctx + noise): 128 CTAs
__global__ __launch_bounds__(256, 1)
void gemm_v()
{
    const __nv_bfloat16 *aHi, *aLo;
    int pos0;
    if (blockIdx.z) { aHi = g_hidHi; aLo = g_hidLo; pos0 = CTX; }
    else            { aHi = g_tgtHi; aLo = g_tgtLo; pos0 = 0; }
    gemm_core<2>(aHi, aLo, g_WvHi, g_WvLo, blockIdx.y * TM, blockIdx.x * TN,
                 HDIM, nullptr, 0, pos0, nullptr, nullptr);
}

// Output projection
__global__ __launch_bounds__(256, 1)
void gemm_out(float* __restrict__ C)
{
    const int bm = blockIdx.y * TM;
    const int bn = blockIdx.x * TN;
    gemm_core<0>(g_AHi, g_ALo, g_WoHi, g_WoLo, bm, bn, HDIM, C, HDIM, 0,
                 nullptr, nullptr);
}

// ---------------------------------------------------------------------------
// Fused fp32 -> (bf16 hi, bf16 lo) split for all six tensors, one launch.
// ---------------------------------------------------------------------------
#define SEG0 8192
#define SEG1 16384
#define SEG2 32768
#define SEG3 36864
#define SEG4 40960
#define SEG5 57344

__global__ __launch_bounds__(256, 1)
void cvt_all(const float4* __restrict__ hid, const float4* __restrict__ tgt,
             const float4* __restrict__ Wq, const float4* __restrict__ Wk,
             const float4* __restrict__ Wv, const float4* __restrict__ Wo)
{
    const int b = blockIdx.x;
    const float4* src;
    __nv_bfloat162 *hi, *lo;
    int off;
    if (b < SEG0)      { src = hid; hi = (__nv_bfloat162*)g_hidHi; lo = (__nv_bfloat162*)g_hidLo; off = b; }
    else if (b < SEG1) { src = tgt; hi = (__nv_bfloat162*)g_tgtHi; lo = (__nv_bfloat162*)g_tgtLo; off = b - SEG0; }
    else if (b < SEG2) { src = Wq;  hi = (__nv_bfloat162*)g_WqHi;  lo = (__nv_bfloat162*)g_WqLo;  off = b - SEG1; }
    else if (b < SEG3) { src = Wk;  hi = (__nv_bfloat162*)g_WkHi;  lo = (__nv_bfloat162*)g_WkLo;  off = b - SEG2; }
    else if (b < SEG4) { src = Wv;  hi = (__nv_bfloat162*)g_WvHi;  lo = (__nv_bfloat162*)g_WvLo;  off = b - SEG3; }
    else               { src = Wo;  hi = (__nv_bfloat162*)g_WoHi;  lo = (__nv_bfloat162*)g_WoLo;  off = b - SEG4; }

    const int i = off * 256 + threadIdx.x;
    float4 v = src[i];
    uint32_t h0, l0, h1, l1;
    bsplit2(v.x, v.y, h0, l0);
    bsplit2(v.z, v.w, h1, l1);
    ((uint32_t*)hi)[2 * i + 0] = h0;
    ((uint32_t*)hi)[2 * i + 1] = h1;
    ((uint32_t*)lo)[2 * i + 0] = l0;
    ((uint32_t*)lo)[2 * i + 1] = l1;
}

// ---------------------------------------------------------------------------
// Tensor-core flash attention (bf16 3-pass split, mma.sync).
// RoPE-Q + scale + hi/lo split fused into the Q prologue (reads fp32 g_Q).
// ---------------------------------------------------------------------------
#define BQ 128
#define BKV 64
#define RSTR 272
#define SQ_L 34816
#define SSTG 69632
#define STG_SZ 69632
#define T_KH 0
#define T_KL 17408
#define T_VH 34816
#define T_VL 52224
#define ATTN_SMEM (SSTG + 2 * STG_SZ)

__device__ __forceinline__ void attn_load_kv(
    uint32_t sb, int stage, int tid, int kvh, int kc)
{
    const uint32_t st = sb + SSTG + stage * STG_SZ;
    const size_t base = (size_t)kvh * KVSTRIDE + (size_t)kc * BKV * HD;
    const __nv_bfloat16* srcs[4] = { g_Kh + base, g_Kl + base, g_Vh + base, g_Vl + base };
#pragma unroll
    for (int t = 0; t < 16; t++) {
        int idx = tid + 256 * t;
        int tile = idx >> 10;
        int rem = idx & 1023;
        int r = rem >> 4;
        int c = rem & 15;
        const char* src = (const char*)(srcs[tile] + (size_t)r * HD) + c * 16;
        uint32_t dst = st + tile * 17408 + r * RSTR + c * 16;
        CP_ASYNC16(dst, src);
    }
}

__global__ __launch_bounds__(256, 1)
void attn_mma(const float* __restrict__ Q,
              const float* __restrict__ cosb, const float* __restrict__ sinb,
              __nv_bfloat16* __restrict__ OHi, __nv_bfloat16* __restrict__ OLo)
{
    extern __shared__ char smem[];
    const uint32_t sb = smem_u32(smem);
    const int tid = threadIdx.x;
    const int wid = tid >> 5;
    const int lane = tid & 31;
    const int h  = blockIdx.y;
    const int q0 = blockIdx.x * BQ;
    const int kvh = h >> 2;

    attn_load_kv(sb, 0, tid, kvh, 0);
    CP_COMMIT();

#pragma unroll
    for (int t = 0; t < 8; t++) {
        int idx = tid + 256 * t;
        int r  = idx >> 4;
        int c4 = (idx & 15) * 4;
        const int pos = CTX + q0 + r;
        const float* qp = Q + (size_t)(q0 + r) * HDIM + h * HD;
        float4 x1 = *(const float4*)(qp + c4);
        float4 x2 = *(const float4*)(qp + c4 + 64);
        float4 c1 = *(const float4*)(cosb + (size_t)pos * HD + c4);
        float4 s1 = *(const float4*)(sinb + (size_t)pos * HD + c4);
        float4 c2 = *(const float4*)(cosb + (size_t)pos * HD + c4 + 64);
        float4 s2 = *(const float4*)(sinb + (size_t)pos * HD + c4 + 64);
        float y1a = (x1.x * c1.x - x2.x * s1.x) * QSCALE;
        float y1b = (x1.y * c1.y - x2.y * s1.y) * QSCALE;
        float y1c = (x1.z * c1.z - x2.z * s1.z) * QSCALE;
        float y1d = (x1.w * c1.w - x2.w * s1.w) * QSCALE;
        float y2a = (x2.x * c2.x + x1.x * s2.x) * QSCALE;
        float y2b = (x2.y * c2.y + x1.y * s2.y) * QSCALE;
        float y2c = (x2.z * c2.z + x1.z * s2.z) * QSCALE;
        float y2d = (x2.w * c2.w + x1.w * s2.w) * QSCALE;
        uint32_t h0, l0, h1, l1, h2, l2, h3, l3;
        bsplit2(y1a, y1b, h0, l0);
        bsplit2(y1c, y1d, h1, l1);
        bsplit2(y2a, y2b, h2, l2);
        bsplit2(y2c, y2d, h3, l3);
        uint32_t d1 = sb + r * RSTR + c4 * 2;
        uint32_t d2 = d1 + 128;
        asm volatile("st.shared.v2.b32 [%0], {%1, %2};" :: "r"(d1), "r"(h0), "r"(h1) : "memory");
        asm volatile("st.shared.v2.b32 [%0], {%1, %2};" :: "r"(d1 + SQ_L), "r"(l0), "r"(l1) : "memory");
        asm volatile("st.shared.v2.b32 [%0], {%1, %2};" :: "r"(d2), "r"(h2), "r"(h3) : "memory");
        asm volatile("st.shared.v2.b32 [%0], {%1, %2};" :: "r"(d2 + SQ_L), "r"(l2), "r"(l3) : "memory");
    }

    float o[16][4];
#pragma unroll
    for (int nt = 0; nt < 16; nt++)
#pragma unroll
        for (int i = 0; i < 4; i++) o[nt][i] = 0.0f;
    float m0 = -INFINITY, m1 = -INFINITY, l0 = 0.0f, l1 = 0.0f;

    const int NCH = KVLEN / BKV;
    for (int kc = 0; kc < NCH; kc++) {
        if (kc + 1 < NCH) attn_load_kv(sb, (kc + 1) & 1, tid, kvh, kc + 1);
        CP_COMMIT();
        CP_WAIT1();
        __syncthreads();

        const uint32_t st = sb + SSTG + (kc & 1) * STG_SZ;

        float s[8][4];
#pragma unroll
        for (int nt = 0; nt < 8; nt++)
#pragma unroll
            for (int i = 0; i < 4; i++) s[nt][i] = 0.0f;

#pragma unroll
        for (int d16 = 0; d16 < 8; d16++) {
            uint32_t qhf[4], qlf[4];
            const int arow = wid * 16 + (lane & 15);
            const int acol = d16 * 16 + (lane >> 4) * 8;
            uint32_t aaddr = sb + arow * RSTR + acol * 2;
            LDSM_X4(qhf[0], qhf[1], qhf[2], qhf[3], aaddr);
            LDSM_X4(qlf[0], qlf[1], qlf[2], qlf[3], aaddr + SQ_L);
            const int bcol = d16 * 16 + ((lane >> 3) & 1) * 8;
#pragma unroll
            for (int nt2 = 0; nt2 < 4; nt2++) {
                uint32_t bh[4], bl[4];
                const int brow = nt2 * 16 + (lane & 7) + (lane >> 4) * 8;
                uint32_t baddr = st + T_KH + brow * RSTR + bcol * 2;
                LDSM_X4(bh[0], bh[1], bh[2], bh[3], baddr);
                LDSM_X4(bl[0], bl[1], bl[2], bl[3], baddr + (T_KL - T_KH));
                MMA16816(s[2 * nt2],     qhf, &bh[0]);
                MMA16816(s[2 * nt2 + 1], qhf, &bh[2]);
                MMA16816(s[2 * nt2],     qhf, &bl[0]);
                MMA16816(s[2 * nt2 + 1], qhf, &bl[2]);
                MMA16816(s[2 * nt2],     qlf, &bh[0]);
                MMA16816(s[2 * nt2 + 1], qlf, &bh[2]);
            }
        }

        float mloc0 = -INFINITY, mloc1 = -INFINITY;
#pragma unroll
        for (int nt = 0; nt < 8; nt++) {
            mloc0 = fmaxf(mloc0, fmaxf(s[nt][0], s[nt][1]));
            mloc1 = fmaxf(mloc1, fmaxf(s[nt][2], s[nt][3]));
        }
        mloc0 = fmaxf(mloc0, __shfl_xor_sync(0xffffffffu, mloc0, 1));
        mloc0 = fmaxf(mloc0, __shfl_xor_sync(0xffffffffu, mloc0, 2));
        mloc1 = fmaxf(mloc1, __shfl_xor_sync(0xffffffffu, mloc1, 1));
        mloc1 = fmaxf(mloc1, __shfl_xor_sync(0xffffffffu, mloc1, 2));
        float mn0 = fmaxf(m0, mloc0), mn1 = fmaxf(m1, mloc1);
        float a0 = exp2f(m0 - mn0), a1 = exp2f(m1 - mn1);
        m0 = mn0; m1 = mn1;

        float ll0 = 0.0f, ll1 = 0.0f;
        uint32_t ph[4][4], pl[4][4];
#pragma unroll
        for (int nt = 0; nt < 8; nt++) {
            float p0 = exp2f(s[nt][0] - mn0);
            float p1 = exp2f(s[nt][1] - mn0);
            float p2 = exp2f(s[nt][2] - mn1);
            float p3 = exp2f(s[nt][3] - mn1);
            ll0 += p0 + p1; ll1 += p2 + p3;
            uint32_t hA, lA, hB, lB;
            bsplit2(p0, p1, hA, lA);
            bsplit2(p2, p3, hB, lB);
            const int kp = nt >> 1, hi8 = (nt & 1) * 2;
            ph[kp][hi8] = hA; ph[kp][hi8 + 1] = hB;
            pl[kp][hi8] = lA; pl[kp][hi8 + 1] = lB;
        }
        ll0 += __shfl_xor_sync(0xffffffffu, ll0, 1);
        ll0 += __shfl_xor_sync(0xffffffffu, ll0, 2);
        ll1 += __shfl_xor_sync(0xffffffffu, ll1, 1);
        ll1 += __shfl_xor_sync(0xffffffffu, ll1, 2);
        l0 = l0 * a0 + ll0;
        l1 = l1 * a1 + ll1;
#pragma unroll
        for (int nt = 0; nt < 16; nt++) {
            o[nt][0] *= a0; o[nt][1] *= a0;
            o[nt][2] *= a1; o[nt][3] *= a1;
        }

#pragma unroll
        for (int kp = 0; kp < 4; kp++) {
            const int vrow = kp * 16 + (lane & 7) + ((lane >> 3) & 1) * 8;
#pragma unroll
            for (int nt2 = 0; nt2 < 8; nt2++) {
                uint32_t vh[4], vl[4];
                const int vcol = nt2 * 16 + (lane >> 4) * 8;
                uint32_t vaddr = st + T_VH + vrow * RSTR + vcol * 2;
                LDSM_X4_T(vh[0], vh[1], vh[2], vh[3], vaddr);
                LDSM_X4_T(vl[0], vl[1], vl[2], vl[3], vaddr + (T_VL - T_VH));
                MMA16816(o[2 * nt2],     ph[kp], &vh[0]);
                MMA16816(o[2 * nt2 + 1], ph[kp], &vh[2]);
                MMA16816(o[2 * nt2],     ph[kp], &vl[0]);
                MMA16816(o[2 * nt2 + 1], ph[kp], &vl[2]);
                MMA16816(o[2 * nt2],     pl[kp], &vh[0]);
                MMA16816(o[2 * nt2 + 1], pl[kp], &vh[2]);
            }
        }
        __syncthreads();
    }

    const float inv0 = 1.0f / l0, inv1 = 1.0f / l1;
    const int row0 = q0 + wid * 16 + (lane >> 2);
#pragma unroll
    for (int nt = 0; nt < 16; nt++) {
        const int col = nt * 8 + (lane & 3) * 2;
        const size_t idx0 = ((size_t)row0 * HDIM + h * HD + col) >> 1;
        const size_t idx1 = ((size_t)(row0 + 8) * HDIM + h * HD + col) >> 1;
        uint32_t h0, l0w, h1, l1w;
        bsplit2(o[nt][0] * inv0, o[nt][1] * inv0, h0, l0w);
        bsplit2(o[nt][2] * inv1, o[nt][3] * inv1, h1, l1w);
        ((uint32_t*)OHi)[idx0] = h0;
        ((uint32_t*)OLo)[idx0] = l0w;
        ((uint32_t*)OHi)[idx1] = h1;
        ((uint32_t*)OLo)[idx1] = l1w;
    }
}

// ---------------------------------------------------------------------------
// Launch
// ---------------------------------------------------------------------------
extern "C" void kernel_launch(void* const* d_in, const int* in_sizes, int n_in,
                              void* d_out, int out_size)
{
    (void)in_sizes; (void)n_in; (void)out_size;
    const float* hidden = (const float*)d_in[0];
    const float* target = (const float*)d_in[1];
    const float* cosb   = (const float*)d_in[2];
    const float* sinb   = (const float*)d_in[3];
    float* out = (float*)d_out;

    float* Qp;
    cudaGetSymbolAddress((void**)&Qp, g_Q);

    __nv_bfloat16 *AHi, *ALo;
    cudaGetSymbolAddress((void**)&AHi, g_AHi);
    cudaGetSymbolAddress((void**)&ALo, g_ALo);

    cudaFuncSetAttribute(gemm_q,   cudaFuncAttributeMaxDynamicSharedMemorySize, SMEM_G);
    cudaFuncSetAttribute(gemm_k,   cudaFuncAttributeMaxDynamicSharedMemorySize, SMEM_G);
    cudaFuncSetAttribute(gemm_v,   cudaFuncAttributeMaxDynamicSharedMemorySize, SMEM_G);
    cudaFuncSetAttribute(gemm_out, cudaFuncAttributeMaxDynamicSharedMemorySize, SMEM_G);
    cudaFuncSetAttribute(attn_mma, cudaFuncAttributeMaxDynamicSharedMemorySize, ATTN_SMEM);

    // All fp32 -> bf16 hi/lo splits in one launch
    cvt_all<<<SEG5, 256>>>((const float4*)hidden, (const float4*)target,
                           (const float4*)d_in[4], (const float4*)d_in[5],
                           (const float4*)d_in[6], (const float4*)d_in[7]);

    // Projections (per-mode kernels for tight register allocation)
    gemm_q<<<dim3(HDIM / TN, QL / TM), 256, SMEM_G>>>(Qp);
    gemm_k<<<dim3((NKV * HD) / TN, CTX / TM, 2), 256, SMEM_G>>>(cosb, sinb);
    gemm_v<<<dim3((NKV * HD) / TN, CTX / TM, 2), 256, SMEM_G>>>();

    // Flash attention (bf16 3-pass, RoPE-Q fused); writes bf16 hi/lo for Wo
    attn_mma<<<dim3(QL / BQ, NH), 256, ATTN_SMEM>>>(Qp, cosb, sinb, AHi, ALo);

    // Output projection
    gemm_out<<<dim3(HDIM / TN, QL / TM), 256, SMEM_G>>>(out);
}